// round 1
// baseline (speedup 1.0000x reference)
#include <cuda_runtime.h>
#include <cstdint>

// YoloLayer: x (B, 3*12, G, G) f32 -> out (B, 3*G*G, 12) f32
// out[b][a*G*G + gy*G + gx][c]:
//   c0 = (sig(p0)+gx)*stride, c1 = (sig(p1)+gy)*stride, c2 = sig(p2)
//   c3..5 = min(exp(p3..5),1000)*anchors[a][0..2]   (stride cancels)
//   c6 = p6, c7 = p7, c8 = sig(p8), c9..11 = sig(p9..11)
// where p_attr = x[b][(a*12+attr)][gy][gx], stride = img_size/G.

#define G_  152
#define GG_ (G_ * G_)        // 23104
#define GG4 (GG_ / 4)        // 5776
#define NA_ 3
#define NATTR 12
#define EXP_CLAMP_ 1000.0f

__device__ __forceinline__ float sigmoidf_(float v) {
    return __fdividef(1.0f, 1.0f + __expf(-v));
}

__global__ __launch_bounds__(256)
void yolo_kernel(const float* __restrict__ x,
                 const float* __restrict__ anchors,
                 const int*   __restrict__ img_size_p,
                 float* __restrict__ out,
                 int total4)
{
    int t = blockIdx.x * blockDim.x + threadIdx.x;
    if (t >= total4) return;

    // img_size may arrive as int32 or float32 bits; 608 as float bits is huge as int.
    int ibits = img_size_p[0];
    float img = (ibits >= 1 && ibits <= (1 << 20)) ? (float)ibits : __int_as_float(ibits);
    const float stride = img / (float)G_;

    // t -> (ba, s4): ba = b*3 + a in [0, B*3), s = 4*s4 spatial index
    int s4 = t % GG4;
    int ba = t / GG4;
    int a  = ba - (ba / NA_) * NA_;      // ba % 3
    int s  = s4 * 4;
    int gy = s / G_;
    int gx = s - gy * G_;                // multiple of 4; gx+3 <= 151 (152 % 4 == 0)

    const float an0 = anchors[a * 5 + 0];
    const float an1 = anchors[a * 5 + 1];
    const float an2 = anchors[a * 5 + 2];

    // 12 channel-strided, spatially-contiguous float4 loads (16B aligned: GG_*4 % 16 == 0)
    const float* base = x + (size_t)ba * NATTR * GG_ + s;
    float4 p[NATTR];
#pragma unroll
    for (int attr = 0; attr < NATTR; ++attr)
        p[attr] = *reinterpret_cast<const float4*>(base + (size_t)attr * GG_);

    const float* pf = reinterpret_cast<const float*>(p);  // pf[attr*4 + j]

    // out flat offset for point j: ((b*N + a*GG + s+j)*12) = (ba*GG + s + j)*12
    float4* ov = reinterpret_cast<float4*>(out + ((size_t)ba * GG_ + s) * NATTR);

    const float fgy_s = (float)gy * stride;

#pragma unroll
    for (int j = 0; j < 4; ++j) {
        float c0 = (sigmoidf_(pf[0 * 4 + j]) + (float)(gx + j)) * stride;
        float c1 =  sigmoidf_(pf[1 * 4 + j]) * stride + fgy_s;
        float c2 =  sigmoidf_(pf[2 * 4 + j]);
        float c3 = fminf(__expf(pf[3 * 4 + j]), EXP_CLAMP_) * an0;
        float c4 = fminf(__expf(pf[4 * 4 + j]), EXP_CLAMP_) * an1;
        float c5 = fminf(__expf(pf[5 * 4 + j]), EXP_CLAMP_) * an2;
        float c6 = pf[6 * 4 + j];
        float c7 = pf[7 * 4 + j];
        float c8 = sigmoidf_(pf[8 * 4 + j]);
        float c9  = sigmoidf_(pf[9  * 4 + j]);
        float c10 = sigmoidf_(pf[10 * 4 + j]);
        float c11 = sigmoidf_(pf[11 * 4 + j]);

        ov[j * 3 + 0] = make_float4(c0, c1, c2,  c3);
        ov[j * 3 + 1] = make_float4(c4, c5, c6,  c7);
        ov[j * 3 + 2] = make_float4(c8, c9, c10, c11);
    }
}

extern "C" void kernel_launch(void* const* d_in, const int* in_sizes, int n_in,
                              void* d_out, int out_size)
{
    const float* x        = (const float*)d_in[0];
    const float* anchors  = (const float*)d_in[1];
    const int*   img_size = (const int*)d_in[2];
    float* out = (float*)d_out;

    // B from x element count: B * 3 * 12 * G * G
    int B = in_sizes[0] / (NA_ * NATTR * GG_);
    int total4 = B * NA_ * GG4;           // threads, 4 spatial points each

    int block = 256;
    int grid = (total4 + block - 1) / block;
    yolo_kernel<<<grid, block>>>(x, anchors, img_size, out, total4);
}

// round 2
// speedup vs baseline: 2.1119x; 2.1119x over previous
#include <cuda_runtime.h>
#include <cstdint>

// YoloLayer: x (B, 3*12, G, G) f32 -> out (B, 3*G*G, 12) f32
// One output point per thread: 12 coalesced scalar loads, 3 float4 stores.

#define G_  152
#define GG_ (G_ * G_)        // 23104
#define NA_ 3
#define NATTR 12
#define EXP_CLAMP_ 1000.0f

__device__ __forceinline__ float sigmoidf_(float v) {
    return __fdividef(1.0f, 1.0f + __expf(-v));
}

__global__ __launch_bounds__(256)
void yolo_kernel(const float* __restrict__ x,
                 const float* __restrict__ anchors,
                 const int*   __restrict__ img_size_p,
                 float* __restrict__ out,
                 int total)
{
    int t = blockIdx.x * blockDim.x + threadIdx.x;
    if (t >= total) return;

    // img_size may arrive as int32 or float32 bits; 608 as float bits is huge as int.
    int ibits = img_size_p[0];
    float img = (ibits >= 1 && ibits <= (1 << 20)) ? (float)ibits : __int_as_float(ibits);
    const float stride = img / (float)G_;

    // t -> (ba, s): ba = b*3 + a, s = spatial index in [0, G*G)
    int s  = t % GG_;
    int ba = t / GG_;
    int a  = ba - (ba / NA_) * NA_;      // ba % 3
    int gy = s / G_;
    int gx = s - gy * G_;

    const float an0 = anchors[a * 5 + 0];
    const float an1 = anchors[a * 5 + 1];
    const float an2 = anchors[a * 5 + 2];

    // 12 channel-strided scalar loads; lanes consecutive in s -> each a full 128B line.
    const float* base = x + (size_t)ba * NATTR * GG_ + s;
    float p[NATTR];
#pragma unroll
    for (int attr = 0; attr < NATTR; ++attr)
        p[attr] = __ldcs(base + (size_t)attr * GG_);

    float c0 = (sigmoidf_(p[0]) + (float)gx) * stride;
    float c1 = (sigmoidf_(p[1]) + (float)gy) * stride;
    float c2 =  sigmoidf_(p[2]);
    float c3 = fminf(__expf(p[3]), EXP_CLAMP_) * an0;   // (anchor/stride)*stride cancels
    float c4 = fminf(__expf(p[4]), EXP_CLAMP_) * an1;
    float c5 = fminf(__expf(p[5]), EXP_CLAMP_) * an2;
    float c6 = p[6];
    float c7 = p[7];
    float c8 = sigmoidf_(p[8]);
    float c9  = sigmoidf_(p[9]);
    float c10 = sigmoidf_(p[10]);
    float c11 = sigmoidf_(p[11]);

    // out offset: (ba*GG + s) * 12 floats; 48B per thread, contiguous, 16B aligned.
    float4* ov = reinterpret_cast<float4*>(out + ((size_t)ba * GG_ + s) * NATTR);
    __stcs(ov + 0, make_float4(c0, c1, c2,  c3));
    __stcs(ov + 1, make_float4(c4, c5, c6,  c7));
    __stcs(ov + 2, make_float4(c8, c9, c10, c11));
}

extern "C" void kernel_launch(void* const* d_in, const int* in_sizes, int n_in,
                              void* d_out, int out_size)
{
    const float* x        = (const float*)d_in[0];
    const float* anchors  = (const float*)d_in[1];
    const int*   img_size = (const int*)d_in[2];
    float* out = (float*)d_out;

    int B = in_sizes[0] / (NA_ * NATTR * GG_);
    int total = B * NA_ * GG_;            // one point per thread

    int block = 256;
    int grid = (total + block - 1) / block;
    yolo_kernel<<<grid, block>>>(x, anchors, img_size, out, total);
}

// round 3
// speedup vs baseline: 2.4824x; 1.1754x over previous
#include <cuda_runtime.h>
#include <cstdint>

// YoloLayer: x (B, 3*12, G, G) f32 -> out (B, 3*G*G, 12) f32
// One point per thread; results staged in smem so global stores are
// perfectly coalesced float4 streams (output flat offset = t*12).

#define G_  152
#define GG_ (G_ * G_)        // 23104
#define NA_ 3
#define NATTR 12
#define EXP_CLAMP_ 1000.0f
#define BLK 256

__device__ __forceinline__ float sigmoidf_(float v) {
    return __fdividef(1.0f, 1.0f + __expf(-v));
}

__global__ __launch_bounds__(BLK)
void yolo_kernel(const float* __restrict__ x,
                 const float* __restrict__ anchors,
                 const int*   __restrict__ img_size_p,
                 float* __restrict__ out,
                 int total)
{
    __shared__ float sbuf[BLK * NATTR];   // 12 KB, mirrors output layout for this block

    int t = blockIdx.x * BLK + threadIdx.x;

    // img_size may arrive as int32 or float32 bits.
    int ibits = img_size_p[0];
    float img = (ibits >= 1 && ibits <= (1 << 20)) ? (float)ibits : __int_as_float(ibits);
    const float stride = img / (float)G_;

    if (t < total) {
        // t -> (ba, s)
        int s  = t % GG_;
        int ba = t / GG_;
        int a  = ba - (ba / NA_) * NA_;      // ba % 3
        int gy = s / G_;
        int gx = s - gy * G_;

        const float an0 = anchors[a * 5 + 0];
        const float an1 = anchors[a * 5 + 1];
        const float an2 = anchors[a * 5 + 2];

        // 12 channel-strided scalar loads; lanes consecutive in s -> full 128B lines.
        const float* base = x + (size_t)ba * NATTR * GG_ + s;
        float p[NATTR];
#pragma unroll
        for (int attr = 0; attr < NATTR; ++attr)
            p[attr] = __ldcs(base + (size_t)attr * GG_);

        float c0 = (sigmoidf_(p[0]) + (float)gx) * stride;
        float c1 = (sigmoidf_(p[1]) + (float)gy) * stride;
        float c2 =  sigmoidf_(p[2]);
        float c3 = fminf(__expf(p[3]), EXP_CLAMP_) * an0;   // (anchor/stride)*stride cancels
        float c4 = fminf(__expf(p[4]), EXP_CLAMP_) * an1;
        float c5 = fminf(__expf(p[5]), EXP_CLAMP_) * an2;

        float4* sv = reinterpret_cast<float4*>(sbuf + threadIdx.x * NATTR);
        sv[0] = make_float4(c0, c1, c2, c3);
        sv[1] = make_float4(c4, c5, p[6], p[7]);
        sv[2] = make_float4(sigmoidf_(p[8]), sigmoidf_(p[9]),
                            sigmoidf_(p[10]), sigmoidf_(p[11]));
    }
    __syncthreads();

    // Stream the block's 12 KB out coalesced: 3 chunks of 256 float4s.
    size_t blockBase = (size_t)blockIdx.x * BLK * NATTR;   // in floats
    const float4* sv4 = reinterpret_cast<const float4*>(sbuf);
    size_t totalF = (size_t)total * NATTR;
#pragma unroll
    for (int k = 0; k < 3; ++k) {
        size_t fo = blockBase + (size_t)(k * BLK + threadIdx.x) * 4;   // float offset
        if (fo < totalF)
            __stcs(reinterpret_cast<float4*>(out + fo), sv4[k * BLK + threadIdx.x]);
    }
}

extern "C" void kernel_launch(void* const* d_in, const int* in_sizes, int n_in,
                              void* d_out, int out_size)
{
    const float* x        = (const float*)d_in[0];
    const float* anchors  = (const float*)d_in[1];
    const int*   img_size = (const int*)d_in[2];
    float* out = (float*)d_out;

    int B = in_sizes[0] / (NA_ * NATTR * GG_);
    int total = B * NA_ * GG_;            // one point per thread

    int grid = (total + BLK - 1) / BLK;
    yolo_kernel<<<grid, BLK>>>(x, anchors, img_size, out, total);
}